// round 2
// baseline (speedup 1.0000x reference)
#include <cuda_runtime.h>
#include <cstdint>

// ============================================================================
// RangeLinearQuantParamLayerWrapper: symmetric 8-bit quantized linear layer
//   1) max|x|, max|W|, max|b|
//   2) quantize x,W -> int8 ; b -> int32 (accumulator scale)
//   3) int8 GEMM (mma.sync m16n8k32 s8, s32 accum) + bias, track max|accum|
//   4) requantize to 8 bits, dequantize to fp32
// All integer math exact => matches fp32 reference (|accum| << 2^24).
// NOTE: tcgen05 is unavailable (harness compiles at plain sm_100 target),
// so the GEMM uses the legacy IMMA path (mma.sync, sm_80+).
// ============================================================================

#define N_DIM 4096
#define K_DIM 4096
#define TOT   16777216   // 4096*4096
#define TOT4  4194304    // TOT/4

// ---------------- scratch (device globals: no runtime allocation) ----------
__device__ signed char g_xq[TOT];      // 16 MB quantized activations [M,K]
__device__ signed char g_wq[TOT];      // 16 MB quantized weights     [N,K]
__device__ int         g_bq[N_DIM];    // bias at accumulator scale
__device__ int         g_accum[TOT];   // 64 MB int32 accumulators
__device__ unsigned    g_max[4];       // 0:max|x| 1:max|W| 2:max|b| 3:max|accum|

// ---------------- kernel 0: reset atomic targets ---------------------------
__global__ void reset_kernel() {
    if (threadIdx.x < 4) g_max[threadIdx.x] = 0u;
}

// ---------------- kernel 1: max|.| reduction -------------------------------
__global__ void maxabs_kernel(const float4* __restrict__ p, int n4, int slot) {
    unsigned m = 0u;
    const int stride = gridDim.x * blockDim.x;
    for (int i = blockIdx.x * blockDim.x + threadIdx.x; i < n4; i += stride) {
        float4 v = p[i];
        float a = fmaxf(fmaxf(fabsf(v.x), fabsf(v.y)), fmaxf(fabsf(v.z), fabsf(v.w)));
        m = max(m, __float_as_uint(a));   // nonneg floats order as uints
    }
    m = __reduce_max_sync(0xFFFFFFFFu, m);
    if ((threadIdx.x & 31) == 0) atomicMax(&g_max[slot], m);
}

// ---------------- kernel 2: quantize ---------------------------------------
__device__ __forceinline__ signed char q8(float v, float s) {
    float r = rintf(v * s);               // jnp.round = half-to-even = rintf
    r = fminf(fmaxf(r, -128.0f), 127.0f);
    return (signed char)(int)r;
}

__global__ void quant_kernel(const float4* __restrict__ x4,
                             const float4* __restrict__ w4,
                             const float*  __restrict__ b) {
    const float in_scale = 255.0f / (2.0f * __uint_as_float(g_max[0]));
    const float w_scale  = 255.0f / (2.0f * __uint_as_float(g_max[1]));
    char4* xq4 = (char4*)g_xq;
    char4* wq4 = (char4*)g_wq;
    const int stride = gridDim.x * blockDim.x;
    for (int i = blockIdx.x * blockDim.x + threadIdx.x; i < TOT4; i += stride) {
        float4 v = x4[i];
        xq4[i] = make_char4(q8(v.x, in_scale), q8(v.y, in_scale),
                            q8(v.z, in_scale), q8(v.w, in_scale));
        float4 w = w4[i];
        wq4[i] = make_char4(q8(w.x, w_scale), q8(w.y, w_scale),
                            q8(w.z, w_scale), q8(w.w, w_scale));
    }
    const int gid = blockIdx.x * blockDim.x + threadIdx.x;
    if (gid < N_DIM) {
        const float b_scale = 255.0f / (2.0f * __uint_as_float(g_max[2]));
        const float accum_scale = in_scale * w_scale;
        float base = fminf(fmaxf(rintf(b[gid] * b_scale), -128.0f), 127.0f);
        float r = rintf(base * (accum_scale / b_scale));
        g_bq[gid] = (int)r;  // small exact integer
    }
}

// ---------------- kernel 3: int8 GEMM (mma.sync IMMA) ----------------------
// D[4096,4096] = Xq[4096,4096] @ Wq^T + bq
// CTA tile 128x128, K-chunk 64B, 4-stage cp.async pipeline.
// 8 warps: warp grid 2(m) x 4(n), warp tile 64x32.
// SMEM rows padded to 80B => conflict-free ldmatrix (stride 80B = 20 banks).
#define STAGES      4
#define ROW_B       80
#define A_STAGE     (128 * ROW_B)            // 10240
#define STAGE_BYTES (2 * A_STAGE)            // 20480
#define SMEM_TOTAL  (STAGES * STAGE_BYTES)   // 81920

__device__ __forceinline__ void cp16(uint32_t dst, const void* src) {
    asm volatile("cp.async.cg.shared.global [%0], [%1], 16;" :: "r"(dst), "l"(src));
}

__device__ __forceinline__ void ldm_x4(uint32_t* r, uint32_t addr) {
    asm volatile("ldmatrix.sync.aligned.m8n8.x4.shared.b16 {%0,%1,%2,%3}, [%4];"
                 : "=r"(r[0]), "=r"(r[1]), "=r"(r[2]), "=r"(r[3]) : "r"(addr));
}

__device__ __forceinline__ void mma_s8(int* c, const uint32_t* a,
                                       uint32_t b0, uint32_t b1) {
    asm volatile(
        "mma.sync.aligned.m16n8k32.row.col.s32.s8.s8.s32 "
        "{%0,%1,%2,%3}, {%4,%5,%6,%7}, {%8,%9}, {%0,%1,%2,%3};"
        : "+r"(c[0]), "+r"(c[1]), "+r"(c[2]), "+r"(c[3])
        : "r"(a[0]), "r"(a[1]), "r"(a[2]), "r"(a[3]), "r"(b0), "r"(b1));
}

__global__ void __launch_bounds__(256, 1) gemm_kernel() {
    extern __shared__ char smem[];
    const uint32_t sb = (uint32_t)__cvta_generic_to_shared(smem);
    const int tid = threadIdx.x;
    const int lane = tid & 31, wid = tid >> 5;
    const int warp_m = wid >> 2;          // 0..1
    const int warp_n = wid & 3;           // 0..3
    const int m_base = (int)blockIdx.y << 7;
    const int n_base = (int)blockIdx.x << 7;

    const signed char* Ag = g_xq + (size_t)m_base * K_DIM;
    const signed char* Bg = g_wq + (size_t)n_base * K_DIM;

    // per-thread cp.async mapping: 512 16B-chunks per operand per stage
    const int c0 = tid, c1 = tid + 256;
    const int r0 = c0 >> 2, q0 = (c0 & 3) << 4;
    const int r1 = c1 >> 2, q1 = (c1 & 3) << 4;

    auto load_stage = [&](int k) {
        const uint32_t st = sb + (k & (STAGES - 1)) * STAGE_BYTES;
        const int kof = k << 6;
        cp16(st + r0 * ROW_B + q0,           Ag + (size_t)r0 * K_DIM + kof + q0);
        cp16(st + r1 * ROW_B + q1,           Ag + (size_t)r1 * K_DIM + kof + q1);
        cp16(st + A_STAGE + r0 * ROW_B + q0, Bg + (size_t)r0 * K_DIM + kof + q0);
        cp16(st + A_STAGE + r1 * ROW_B + q1, Bg + (size_t)r1 * K_DIM + kof + q1);
    };

    // ldmatrix lane-address components
    const int a_row_l = warp_m * 64 + (lane & 7) + ((lane >> 3) & 1) * 8;
    const int a_k_l   = ((lane >> 4) & 1) * 16;
    const int b_row_l = warp_n * 32 + (lane & 7) + ((lane >> 4) & 1) * 8;
    const int b_k_l   = ((lane >> 3) & 1) * 16;

    int acc[4][4][4];
    #pragma unroll
    for (int i = 0; i < 4; i++)
        #pragma unroll
        for (int j = 0; j < 4; j++)
            #pragma unroll
            for (int l = 0; l < 4; l++) acc[i][j][l] = 0;

    load_stage(0); asm volatile("cp.async.commit_group;" ::: "memory");
    load_stage(1); asm volatile("cp.async.commit_group;" ::: "memory");
    load_stage(2); asm volatile("cp.async.commit_group;" ::: "memory");

    for (int k = 0; k < 64; k++) {
        asm volatile("cp.async.wait_group 2;" ::: "memory");
        __syncthreads();
        if (k + 3 < 64) load_stage(k + 3);
        asm volatile("cp.async.commit_group;" ::: "memory");

        const uint32_t sa  = sb + (k & (STAGES - 1)) * STAGE_BYTES;
        const uint32_t sbb = sa + A_STAGE;

        #pragma unroll
        for (int ks = 0; ks < 2; ks++) {
            uint32_t ar[4][4];
            #pragma unroll
            for (int fm = 0; fm < 4; fm++)
                ldm_x4(ar[fm], sa + (uint32_t)(a_row_l + fm * 16) * ROW_B
                                  + a_k_l + ks * 32);
            uint32_t br[2][4];
            #pragma unroll
            for (int fp = 0; fp < 2; fp++)
                ldm_x4(br[fp], sbb + (uint32_t)(b_row_l + fp * 16) * ROW_B
                                   + b_k_l + ks * 32);
            #pragma unroll
            for (int fm = 0; fm < 4; fm++)
                #pragma unroll
                for (int fn = 0; fn < 4; fn++)
                    mma_s8(acc[fm][fn], ar[fm],
                           br[fn >> 1][(fn & 1) * 2],
                           br[fn >> 1][(fn & 1) * 2 + 1]);
        }
    }

    // ---- epilogue: bias add, store int32 accum, track max|accum| ----------
    const int g = lane >> 2, t4 = lane & 3;
    const int m0r = m_base + warp_m * 64;
    const int n0c = n_base + warp_n * 32;
    unsigned lm = 0u;
    #pragma unroll
    for (int fn = 0; fn < 4; fn++) {
        const int col = n0c + fn * 8 + t4 * 2;
        const int b0v = g_bq[col], b1v = g_bq[col + 1];
        #pragma unroll
        for (int fm = 0; fm < 4; fm++) {
            const int row = m0r + fm * 16 + g;
            int v0 = acc[fm][fn][0] + b0v;
            int v1 = acc[fm][fn][1] + b1v;
            int v2 = acc[fm][fn][2] + b0v;
            int v3 = acc[fm][fn][3] + b1v;
            *(int2*)&g_accum[(size_t)row * N_DIM + col]       = make_int2(v0, v1);
            *(int2*)&g_accum[(size_t)(row + 8) * N_DIM + col] = make_int2(v2, v3);
            lm = max(lm, (unsigned)(v0 < 0 ? -v0 : v0));
            lm = max(lm, (unsigned)(v1 < 0 ? -v1 : v1));
            lm = max(lm, (unsigned)(v2 < 0 ? -v2 : v2));
            lm = max(lm, (unsigned)(v3 < 0 ? -v3 : v3));
        }
    }
    lm = __reduce_max_sync(0xFFFFFFFFu, lm);
    if (lane == 0) atomicMax(&g_max[3], lm);
}

// ---------------- kernel 4: requantize + dequantize ------------------------
__global__ void requant_kernel(float4* __restrict__ out4) {
    const float in_scale = 255.0f / (2.0f * __uint_as_float(g_max[0]));
    const float w_scale  = 255.0f / (2.0f * __uint_as_float(g_max[1]));
    const float accum_scale = in_scale * w_scale;
    const float max_acc = (float)g_max[3];          // exact (< 2^24)
    const float out_sat = max_acc / accum_scale;
    const float out_scale = 255.0f / (2.0f * out_sat);
    const float ratio = out_scale / accum_scale;
    const int4* a4 = (const int4*)g_accum;
    const int stride = gridDim.x * blockDim.x;
    for (int i = blockIdx.x * blockDim.x + threadIdx.x; i < TOT4; i += stride) {
        int4 a = a4[i];
        float4 o;
        o.x = fminf(fmaxf(rintf((float)a.x * ratio), -128.0f), 127.0f) / out_scale;
        o.y = fminf(fmaxf(rintf((float)a.y * ratio), -128.0f), 127.0f) / out_scale;
        o.z = fminf(fmaxf(rintf((float)a.z * ratio), -128.0f), 127.0f) / out_scale;
        o.w = fminf(fmaxf(rintf((float)a.w * ratio), -128.0f), 127.0f) / out_scale;
        out4[i] = o;
    }
}

// ---------------- launch ----------------------------------------------------
extern "C" void kernel_launch(void* const* d_in, const int* in_sizes, int n_in,
                              void* d_out, int out_size) {
    const float* x = (const float*)d_in[0];
    const float* W = (const float*)d_in[1];
    const float* b = (const float*)d_in[2];

    cudaFuncSetAttribute(gemm_kernel,
                         cudaFuncAttributeMaxDynamicSharedMemorySize, SMEM_TOTAL);

    reset_kernel<<<1, 32>>>();
    maxabs_kernel<<<1024, 256>>>((const float4*)x, TOT4, 0);
    maxabs_kernel<<<1024, 256>>>((const float4*)W, TOT4, 1);
    maxabs_kernel<<<4, 256>>>((const float4*)b, N_DIM / 4, 2);
    quant_kernel<<<4096, 256>>>((const float4*)x, (const float4*)W, b);
    gemm_kernel<<<dim3(32, 32), 256, SMEM_TOTAL>>>();
    requant_kernel<<<2048, 256>>>((float4*)d_out);
}

// round 3
// speedup vs baseline: 1.2702x; 1.2702x over previous
#include <cuda_runtime.h>
#include <cstdint>

// ============================================================================
// RangeLinearQuantParamLayerWrapper: symmetric 8-bit quantized linear layer
//   1) max|x|, max|W|, max|b|
//   2) quantize x,W -> int8 ; b -> int32 (accumulator scale)
//   3) int8 GEMM (mma.sync m16n8k32 s8, s32 accum) + bias, track max|accum|
//   4) requantize to 8 bits, dequantize to fp32
// All integer math exact => matches fp32 reference (|accum| << 2^24).
// ============================================================================

#define N_DIM 4096
#define K_DIM 4096
#define TOT   16777216   // 4096*4096
#define TOT4  4194304    // TOT/4

// ---------------- scratch (device globals: no runtime allocation) ----------
__device__ signed char g_xq[TOT];      // quantized activations [M,K]
__device__ signed char g_wq[TOT];      // quantized weights     [N,K]
__device__ int         g_bq[N_DIM];    // bias at accumulator scale
__device__ int         g_accum[TOT];   // int32 accumulators
__device__ unsigned    g_max[4];       // 0:max|x| 1:max|W| 2:max|b| 3:max|accum|

// ---------------- kernel 0: reset atomic targets ---------------------------
__global__ void reset_kernel() {
    if (threadIdx.x < 4) g_max[threadIdx.x] = 0u;
}

// ---------------- kernel 1: max|.| reduction -------------------------------
__global__ void maxabs_kernel(const float4* __restrict__ p, int n4, int slot) {
    unsigned m = 0u;
    const int stride = gridDim.x * blockDim.x;
    for (int i = blockIdx.x * blockDim.x + threadIdx.x; i < n4; i += stride) {
        float4 v = p[i];
        float a = fmaxf(fmaxf(fabsf(v.x), fabsf(v.y)), fmaxf(fabsf(v.z), fabsf(v.w)));
        m = max(m, __float_as_uint(a));   // nonneg floats order as uints
    }
    m = __reduce_max_sync(0xFFFFFFFFu, m);
    if ((threadIdx.x & 31) == 0) atomicMax(&g_max[slot], m);
}

// ---------------- kernel 2: quantize ---------------------------------------
__device__ __forceinline__ signed char q8(float v, float s) {
    float r = rintf(v * s);               // jnp.round = half-to-even = rintf
    r = fminf(fmaxf(r, -128.0f), 127.0f);
    return (signed char)(int)r;
}

__global__ void quant_kernel(const float4* __restrict__ x4,
                             const float4* __restrict__ w4,
                             const float*  __restrict__ b) {
    const float in_scale = 255.0f / (2.0f * __uint_as_float(g_max[0]));
    const float w_scale  = 255.0f / (2.0f * __uint_as_float(g_max[1]));
    char4* xq4 = (char4*)g_xq;
    char4* wq4 = (char4*)g_wq;
    const int stride = gridDim.x * blockDim.x;
    for (int i = blockIdx.x * blockDim.x + threadIdx.x; i < TOT4; i += stride) {
        float4 v = x4[i];
        xq4[i] = make_char4(q8(v.x, in_scale), q8(v.y, in_scale),
                            q8(v.z, in_scale), q8(v.w, in_scale));
        float4 w = w4[i];
        wq4[i] = make_char4(q8(w.x, w_scale), q8(w.y, w_scale),
                            q8(w.z, w_scale), q8(w.w, w_scale));
    }
    const int gid = blockIdx.x * blockDim.x + threadIdx.x;
    if (gid < N_DIM) {
        const float b_scale = 255.0f / (2.0f * __uint_as_float(g_max[2]));
        const float accum_scale = in_scale * w_scale;
        float base = fminf(fmaxf(rintf(b[gid] * b_scale), -128.0f), 127.0f);
        float r = rintf(base * (accum_scale / b_scale));
        g_bq[gid] = (int)r;  // small exact integer
    }
}

// ---------------- kernel 3: int8 GEMM (mma.sync IMMA) ----------------------
// D = Xq @ Wq^T + bq.  CTA tile 128x128, K-chunk 128B, 4-stage cp.async
// pipeline, 16 warps (4m x 4n), warp tile 32x32, XOR-swizzled 128B rows,
// register double-buffered ldmatrix fragments.
#define STAGES      4
#define A_STAGE     16384                    // 128 rows * 128 B
#define STAGE_BYTES 32768                    // A + B
#define SMEM_TOTAL  (STAGES * STAGE_BYTES)   // 131072
#define K_ITERS     32                       // 4096 / 128

__device__ __forceinline__ void cp16(uint32_t dst, const void* src) {
    asm volatile("cp.async.cg.shared.global [%0], [%1], 16;" :: "r"(dst), "l"(src));
}

__device__ __forceinline__ void ldm_x4(uint32_t* r, uint32_t addr) {
    asm volatile("ldmatrix.sync.aligned.m8n8.x4.shared.b16 {%0,%1,%2,%3}, [%4];"
                 : "=r"(r[0]), "=r"(r[1]), "=r"(r[2]), "=r"(r[3]) : "r"(addr));
}

__device__ __forceinline__ void mma_s8(int* c, const uint32_t* a,
                                       uint32_t b0, uint32_t b1) {
    asm volatile(
        "mma.sync.aligned.m16n8k32.row.col.s32.s8.s8.s32 "
        "{%0,%1,%2,%3}, {%4,%5,%6,%7}, {%8,%9}, {%0,%1,%2,%3};"
        : "+r"(c[0]), "+r"(c[1]), "+r"(c[2]), "+r"(c[3])
        : "r"(a[0]), "r"(a[1]), "r"(a[2]), "r"(a[3]), "r"(b0), "r"(b1));
}

// swizzled byte offset within a 128-row x 128B tile
__device__ __forceinline__ uint32_t swz(int row, int kchunk) {
    return (uint32_t)(row * 128 + ((kchunk ^ (row & 7)) << 4));
}

__global__ void __launch_bounds__(512) gemm_kernel() {
    extern __shared__ char smem[];
    const uint32_t sb = (uint32_t)__cvta_generic_to_shared(smem);
    const int tid = threadIdx.x;
    const int lane = tid & 31, wid = tid >> 5;
    const int warp_m = wid >> 2;          // 0..3
    const int warp_n = wid & 3;           // 0..3
    const int m_base = (int)blockIdx.y << 7;
    const int n_base = (int)blockIdx.x << 7;

    const signed char* Ag = g_xq + (size_t)m_base * K_DIM;
    const signed char* Bg = g_wq + (size_t)n_base * K_DIM;

    // cp.async mapping: 1024 chunks per tile per stage / 512 threads
    const int r0 = tid >> 3;              // 0..63
    const int kc = tid & 7;               // 16B chunk within 128B row
    const uint32_t dA0 = swz(r0, kc),      dA1 = swz(r0 + 64, kc);
    const size_t   sA0 = (size_t)r0 * K_DIM + (kc << 4);
    const size_t   sA1 = sA0 + (size_t)64 * K_DIM;

    auto load_stage = [&](int k) {
        const uint32_t st = sb + (k & (STAGES - 1)) * STAGE_BYTES;
        const int kof = k << 7;
        cp16(st + dA0,           Ag + sA0 + kof);
        cp16(st + dA1,           Ag + sA1 + kof);
        cp16(st + A_STAGE + dA0, Bg + sA0 + kof);
        cp16(st + A_STAGE + dA1, Bg + sA1 + kof);
    };

    // ldmatrix lane components (same mapping validated in R1)
    const int a_row = warp_m * 32 + (lane & 7) + ((lane >> 3) & 1) * 8;
    const int a_kch = (lane >> 4) & 1;    // 16B chunk select
    const int b_row = warp_n * 32 + (lane & 7) + ((lane >> 4) & 1) * 8;
    const int b_kch = (lane >> 3) & 1;

    int acc[2][4][4];
    #pragma unroll
    for (int i = 0; i < 2; i++)
        #pragma unroll
        for (int j = 0; j < 4; j++)
            #pragma unroll
            for (int l = 0; l < 4; l++) acc[i][j][l] = 0;

    load_stage(0); asm volatile("cp.async.commit_group;" ::: "memory");
    load_stage(1); asm volatile("cp.async.commit_group;" ::: "memory");
    load_stage(2); asm volatile("cp.async.commit_group;" ::: "memory");

    uint32_t ar[2][2][4];   // [buf][fm][reg]
    uint32_t br[2][2][4];   // [buf][fp][reg]

    for (int k = 0; k < K_ITERS; k++) {
        asm volatile("cp.async.wait_group 2;" ::: "memory");
        __syncthreads();
        if (k + 3 < K_ITERS) load_stage(k + 3);
        asm volatile("cp.async.commit_group;" ::: "memory");

        const uint32_t sa  = sb + (k & (STAGES - 1)) * STAGE_BYTES;
        const uint32_t sbb = sa + A_STAGE;

        // prefetch ks=0 fragments
        #pragma unroll
        for (int fm = 0; fm < 2; fm++)
            ldm_x4(ar[0][fm], sa  + swz(a_row + fm * 16, a_kch));
        #pragma unroll
        for (int fp = 0; fp < 2; fp++)
            ldm_x4(br[0][fp], sbb + swz(b_row + fp * 16, b_kch));

        #pragma unroll
        for (int ks = 0; ks < 4; ks++) {
            const int cur = ks & 1, nxt = cur ^ 1;
            if (ks < 3) {
                const int kn = (ks + 1) * 2;
                #pragma unroll
                for (int fm = 0; fm < 2; fm++)
                    ldm_x4(ar[nxt][fm], sa  + swz(a_row + fm * 16, kn + a_kch));
                #pragma unroll
                for (int fp = 0; fp < 2; fp++)
                    ldm_x4(br[nxt][fp], sbb + swz(b_row + fp * 16, kn + b_kch));
            }
            #pragma unroll
            for (int fm = 0; fm < 2; fm++)
                #pragma unroll
                for (int fn = 0; fn < 4; fn++)
                    mma_s8(acc[fm][fn], ar[cur][fm],
                           br[cur][fn >> 1][(fn & 1) * 2],
                           br[cur][fn >> 1][(fn & 1) * 2 + 1]);
        }
    }

    // ---- epilogue: bias add, store int32 accum, track max|accum| ----------
    const int g = lane >> 2, t4 = lane & 3;
    const int m0r = m_base + warp_m * 32;
    const int n0c = n_base + warp_n * 32;
    unsigned lm = 0u;
    #pragma unroll
    for (int fn = 0; fn < 4; fn++) {
        const int col = n0c + fn * 8 + t4 * 2;
        const int b0v = g_bq[col], b1v = g_bq[col + 1];
        #pragma unroll
        for (int fm = 0; fm < 2; fm++) {
            const int row = m0r + fm * 16 + g;
            int v0 = acc[fm][fn][0] + b0v;
            int v1 = acc[fm][fn][1] + b1v;
            int v2 = acc[fm][fn][2] + b0v;
            int v3 = acc[fm][fn][3] + b1v;
            *(int2*)&g_accum[(size_t)row * N_DIM + col]       = make_int2(v0, v1);
            *(int2*)&g_accum[(size_t)(row + 8) * N_DIM + col] = make_int2(v2, v3);
            lm = max(lm, (unsigned)(v0 < 0 ? -v0 : v0));
            lm = max(lm, (unsigned)(v1 < 0 ? -v1 : v1));
            lm = max(lm, (unsigned)(v2 < 0 ? -v2 : v2));
            lm = max(lm, (unsigned)(v3 < 0 ? -v3 : v3));
        }
    }
    lm = __reduce_max_sync(0xFFFFFFFFu, lm);
    if (lane == 0) atomicMax(&g_max[3], lm);
}

// ---------------- kernel 4: requantize + dequantize ------------------------
__global__ void requant_kernel(float4* __restrict__ out4) {
    const float in_scale = 255.0f / (2.0f * __uint_as_float(g_max[0]));
    const float w_scale  = 255.0f / (2.0f * __uint_as_float(g_max[1]));
    const float accum_scale = in_scale * w_scale;
    const float max_acc = (float)g_max[3];          // exact (< 2^24)
    const float out_sat = max_acc / accum_scale;
    const float out_scale = 255.0f / (2.0f * out_sat);
    const float ratio = out_scale / accum_scale;
    const int4* a4 = (const int4*)g_accum;
    const int stride = gridDim.x * blockDim.x;
    for (int i = blockIdx.x * blockDim.x + threadIdx.x; i < TOT4; i += stride) {
        int4 a = a4[i];
        float4 o;
        o.x = fminf(fmaxf(rintf((float)a.x * ratio), -128.0f), 127.0f) / out_scale;
        o.y = fminf(fmaxf(rintf((float)a.y * ratio), -128.0f), 127.0f) / out_scale;
        o.z = fminf(fmaxf(rintf((float)a.z * ratio), -128.0f), 127.0f) / out_scale;
        o.w = fminf(fmaxf(rintf((float)a.w * ratio), -128.0f), 127.0f) / out_scale;
        out4[i] = o;
    }
}

// ---------------- launch ----------------------------------------------------
extern "C" void kernel_launch(void* const* d_in, const int* in_sizes, int n_in,
                              void* d_out, int out_size) {
    const float* x = (const float*)d_in[0];
    const float* W = (const float*)d_in[1];
    const float* b = (const float*)d_in[2];

    cudaFuncSetAttribute(gemm_kernel,
                         cudaFuncAttributeMaxDynamicSharedMemorySize, SMEM_TOTAL);

    reset_kernel<<<1, 32>>>();
    maxabs_kernel<<<1024, 256>>>((const float4*)x, TOT4, 0);
    maxabs_kernel<<<1024, 256>>>((const float4*)W, TOT4, 1);
    maxabs_kernel<<<4, 256>>>((const float4*)b, N_DIM / 4, 2);
    quant_kernel<<<4096, 256>>>((const float4*)x, (const float4*)W, b);
    gemm_kernel<<<dim3(32, 32), 512, SMEM_TOTAL>>>();
    requant_kernel<<<2048, 256>>>((float4*)d_out);
}

// round 4
// speedup vs baseline: 1.3194x; 1.0387x over previous
#include <cuda_runtime.h>
#include <cstdint>

// ============================================================================
// RangeLinearQuantParamLayerWrapper: symmetric 8-bit quantized linear layer
//   1) max|x|, max|W|, max|b|
//   2) quantize x,W -> int8 ; b -> int32 (accumulator scale)
//   3) int8 GEMM (mma.sync m16n8k32 s8, s32 accum) + bias, track max|accum|
//   4) requantize to 8 bits, dequantize to fp32
// All integer math exact => matches fp32 reference (|accum| << 2^24).
// GEMM: CTA 128x256, 8 warps, warp tile 64x64 (CUTLASS sm80 int8 shape),
// 4-stage cp.async pipeline, XOR-swizzled 128B rows, double-buffered frags.
// ============================================================================

#define N_DIM 4096
#define K_DIM 4096
#define TOT   16777216   // 4096*4096
#define TOT4  4194304    // TOT/4

// ---------------- scratch (device globals: no runtime allocation) ----------
__device__ signed char g_xq[TOT];      // quantized activations [M,K]
__device__ signed char g_wq[TOT];      // quantized weights     [N,K]
__device__ int         g_bq[N_DIM];    // bias at accumulator scale
__device__ int         g_accum[TOT];   // int32 accumulators
__device__ unsigned    g_max[4];       // 0:max|x| 1:max|W| 2:max|b| 3:max|accum|

// ---------------- kernel 0: reset atomic targets ---------------------------
__global__ void reset_kernel() {
    if (threadIdx.x < 4) g_max[threadIdx.x] = 0u;
}

// ---------------- kernel 1: max|.| reduction -------------------------------
__global__ void maxabs_kernel(const float4* __restrict__ p, int n4, int slot) {
    unsigned m = 0u;
    const int stride = gridDim.x * blockDim.x;
    for (int i = blockIdx.x * blockDim.x + threadIdx.x; i < n4; i += stride) {
        float4 v = p[i];
        float a = fmaxf(fmaxf(fabsf(v.x), fabsf(v.y)), fmaxf(fabsf(v.z), fabsf(v.w)));
        m = max(m, __float_as_uint(a));   // nonneg floats order as uints
    }
    m = __reduce_max_sync(0xFFFFFFFFu, m);
    if ((threadIdx.x & 31) == 0) atomicMax(&g_max[slot], m);
}

// ---------------- kernel 2: quantize ---------------------------------------
__device__ __forceinline__ signed char q8(float v, float s) {
    float r = rintf(v * s);               // jnp.round = half-to-even = rintf
    r = fminf(fmaxf(r, -128.0f), 127.0f);
    return (signed char)(int)r;
}

__global__ void quant_kernel(const float4* __restrict__ x4,
                             const float4* __restrict__ w4,
                             const float*  __restrict__ b) {
    const float in_scale = 255.0f / (2.0f * __uint_as_float(g_max[0]));
    const float w_scale  = 255.0f / (2.0f * __uint_as_float(g_max[1]));
    char4* xq4 = (char4*)g_xq;
    char4* wq4 = (char4*)g_wq;
    const int stride = gridDim.x * blockDim.x;
    for (int i = blockIdx.x * blockDim.x + threadIdx.x; i < TOT4; i += stride) {
        float4 v = x4[i];
        xq4[i] = make_char4(q8(v.x, in_scale), q8(v.y, in_scale),
                            q8(v.z, in_scale), q8(v.w, in_scale));
        float4 w = w4[i];
        wq4[i] = make_char4(q8(w.x, w_scale), q8(w.y, w_scale),
                            q8(w.z, w_scale), q8(w.w, w_scale));
    }
    const int gid = blockIdx.x * blockDim.x + threadIdx.x;
    if (gid < N_DIM) {
        const float b_scale = 255.0f / (2.0f * __uint_as_float(g_max[2]));
        const float accum_scale = in_scale * w_scale;
        float base = fminf(fmaxf(rintf(b[gid] * b_scale), -128.0f), 127.0f);
        float r = rintf(base * (accum_scale / b_scale));
        g_bq[gid] = (int)r;  // small exact integer
    }
}

// ---------------- kernel 3: int8 GEMM (mma.sync IMMA) ----------------------
#define STAGES      4
#define A_STAGE     16384                    // 128 rows * 128 B
#define B_STAGE     32768                    // 256 rows * 128 B
#define STAGE_BYTES (A_STAGE + B_STAGE)      // 49152
#define SMEM_TOTAL  (STAGES * STAGE_BYTES)   // 196608
#define K_ITERS     32                       // 4096 / 128

__device__ __forceinline__ void cp16(uint32_t dst, const void* src) {
    asm volatile("cp.async.cg.shared.global [%0], [%1], 16;" :: "r"(dst), "l"(src));
}

__device__ __forceinline__ void ldm_x4(uint32_t* r, uint32_t addr) {
    asm volatile("ldmatrix.sync.aligned.m8n8.x4.shared.b16 {%0,%1,%2,%3}, [%4];"
                 : "=r"(r[0]), "=r"(r[1]), "=r"(r[2]), "=r"(r[3]) : "r"(addr));
}

__device__ __forceinline__ void mma_s8(int* c, const uint32_t* a,
                                       uint32_t b0, uint32_t b1) {
    asm volatile(
        "mma.sync.aligned.m16n8k32.row.col.s32.s8.s8.s32 "
        "{%0,%1,%2,%3}, {%4,%5,%6,%7}, {%8,%9}, {%0,%1,%2,%3};"
        : "+r"(c[0]), "+r"(c[1]), "+r"(c[2]), "+r"(c[3])
        : "r"(a[0]), "r"(a[1]), "r"(a[2]), "r"(a[3]), "r"(b0), "r"(b1));
}

// swizzled byte offset within a tile of 128B rows
__device__ __forceinline__ uint32_t swz(int row, int kchunk) {
    return (uint32_t)(row * 128 + ((kchunk ^ (row & 7)) << 4));
}

__global__ void __launch_bounds__(256, 1) gemm_kernel() {
    extern __shared__ char smem[];
    const uint32_t sb = (uint32_t)__cvta_generic_to_shared(smem);
    const int tid = threadIdx.x;
    const int lane = tid & 31, wid = tid >> 5;
    const int warp_m = wid >> 2;          // 0..1  (64-row slab)
    const int warp_n = wid & 3;           // 0..3  (64-col slab)
    const int m_base = (int)blockIdx.y << 7;   // 32 tiles of 128
    const int n_base = (int)blockIdx.x << 8;   // 16 tiles of 256

    const signed char* Ag = g_xq + (size_t)m_base * K_DIM;
    const signed char* Bg = g_wq + (size_t)n_base * K_DIM;

    // cp.async mapping: A 1024 + B 2048 16B-chunks per stage / 256 threads
    const int r0 = tid >> 3;              // 0..31
    const int kc = tid & 7;               // 16B chunk within 128B row
    const size_t gofs = (size_t)r0 * K_DIM + (kc << 4);

    auto load_stage = [&](int k) {
        const uint32_t st = sb + (k & (STAGES - 1)) * STAGE_BYTES;
        const int kof = k << 7;
        #pragma unroll
        for (int i = 0; i < 4; i++)       // A: rows r0 + 32*i
            cp16(st + swz(r0 + 32 * i, kc),
                 Ag + gofs + (size_t)(32 * i) * K_DIM + kof);
        #pragma unroll
        for (int i = 0; i < 8; i++)       // B: rows r0 + 32*i
            cp16(st + A_STAGE + swz(r0 + 32 * i, kc),
                 Bg + gofs + (size_t)(32 * i) * K_DIM + kof);
    };

    // ldmatrix lane components
    const int a_row = warp_m * 64 + (lane & 7) + ((lane >> 3) & 1) * 8;
    const int a_kch = (lane >> 4) & 1;    // 16B chunk select within 32B step
    const int b_row = warp_n * 64 + (lane & 7) + ((lane >> 4) & 1) * 8;
    const int b_kch = (lane >> 3) & 1;

    int acc[4][8][4];
    #pragma unroll
    for (int i = 0; i < 4; i++)
        #pragma unroll
        for (int j = 0; j < 8; j++)
            #pragma unroll
            for (int l = 0; l < 4; l++) acc[i][j][l] = 0;

    load_stage(0); asm volatile("cp.async.commit_group;" ::: "memory");
    load_stage(1); asm volatile("cp.async.commit_group;" ::: "memory");
    load_stage(2); asm volatile("cp.async.commit_group;" ::: "memory");

    uint32_t ar[2][4][4];   // [buf][fm][reg]
    uint32_t br[2][4][4];   // [buf][fp][reg]

    for (int k = 0; k < K_ITERS; k++) {
        asm volatile("cp.async.wait_group 2;" ::: "memory");
        __syncthreads();
        if (k + 3 < K_ITERS) load_stage(k + 3);
        asm volatile("cp.async.commit_group;" ::: "memory");

        const uint32_t sa  = sb + (k & (STAGES - 1)) * STAGE_BYTES;
        const uint32_t sbb = sa + A_STAGE;

        // prefetch ks=0 fragments
        #pragma unroll
        for (int fm = 0; fm < 4; fm++)
            ldm_x4(ar[0][fm], sa  + swz(a_row + fm * 16, a_kch));
        #pragma unroll
        for (int fp = 0; fp < 4; fp++)
            ldm_x4(br[0][fp], sbb + swz(b_row + fp * 16, b_kch));

        #pragma unroll
        for (int ks = 0; ks < 4; ks++) {  // 4 x 32B K-steps per 128B chunk
            const int cur = ks & 1, nxt = cur ^ 1;
            if (ks < 3) {
                const int kn = (ks + 1) * 2;
                #pragma unroll
                for (int fm = 0; fm < 4; fm++)
                    ldm_x4(ar[nxt][fm], sa  + swz(a_row + fm * 16, kn + a_kch));
                #pragma unroll
                for (int fp = 0; fp < 4; fp++)
                    ldm_x4(br[nxt][fp], sbb + swz(b_row + fp * 16, kn + b_kch));
            }
            #pragma unroll
            for (int fm = 0; fm < 4; fm++)
                #pragma unroll
                for (int fn = 0; fn < 8; fn++)
                    mma_s8(acc[fm][fn], ar[cur][fm],
                           br[cur][fn >> 1][(fn & 1) * 2],
                           br[cur][fn >> 1][(fn & 1) * 2 + 1]);
        }
    }

    // ---- epilogue: bias add, store int32 accum, track max|accum| ----------
    const int g = lane >> 2, t4 = lane & 3;
    const int m0r = m_base + warp_m * 64;
    const int n0c = n_base + warp_n * 64;
    unsigned lm = 0u;
    #pragma unroll
    for (int fn = 0; fn < 8; fn++) {
        const int col = n0c + fn * 8 + t4 * 2;
        const int b0v = g_bq[col], b1v = g_bq[col + 1];
        #pragma unroll
        for (int fm = 0; fm < 4; fm++) {
            const int row = m0r + fm * 16 + g;
            int v0 = acc[fm][fn][0] + b0v;
            int v1 = acc[fm][fn][1] + b1v;
            int v2 = acc[fm][fn][2] + b0v;
            int v3 = acc[fm][fn][3] + b1v;
            *(int2*)&g_accum[(size_t)row * N_DIM + col]       = make_int2(v0, v1);
            *(int2*)&g_accum[(size_t)(row + 8) * N_DIM + col] = make_int2(v2, v3);
            lm = max(lm, (unsigned)(v0 < 0 ? -v0 : v0));
            lm = max(lm, (unsigned)(v1 < 0 ? -v1 : v1));
            lm = max(lm, (unsigned)(v2 < 0 ? -v2 : v2));
            lm = max(lm, (unsigned)(v3 < 0 ? -v3 : v3));
        }
    }
    lm = __reduce_max_sync(0xFFFFFFFFu, lm);
    if (lane == 0) atomicMax(&g_max[3], lm);
}

// ---------------- kernel 4: requantize + dequantize ------------------------
__global__ void requant_kernel(float4* __restrict__ out4) {
    const float in_scale = 255.0f / (2.0f * __uint_as_float(g_max[0]));
    const float w_scale  = 255.0f / (2.0f * __uint_as_float(g_max[1]));
    const float accum_scale = in_scale * w_scale;
    const float max_acc = (float)g_max[3];          // exact (< 2^24)
    const float out_sat = max_acc / accum_scale;
    const float out_scale = 255.0f / (2.0f * out_sat);
    const float ratio = out_scale / accum_scale;
    const int4* a4 = (const int4*)g_accum;
    const int stride = gridDim.x * blockDim.x;
    for (int i = blockIdx.x * blockDim.x + threadIdx.x; i < TOT4; i += stride) {
        int4 a = a4[i];
        float4 o;
        o.x = fminf(fmaxf(rintf((float)a.x * ratio), -128.0f), 127.0f) / out_scale;
        o.y = fminf(fmaxf(rintf((float)a.y * ratio), -128.0f), 127.0f) / out_scale;
        o.z = fminf(fmaxf(rintf((float)a.z * ratio), -128.0f), 127.0f) / out_scale;
        o.w = fminf(fmaxf(rintf((float)a.w * ratio), -128.0f), 127.0f) / out_scale;
        out4[i] = o;
    }
}

// ---------------- launch ----------------------------------------------------
extern "C" void kernel_launch(void* const* d_in, const int* in_sizes, int n_in,
                              void* d_out, int out_size) {
    const float* x = (const float*)d_in[0];
    const float* W = (const float*)d_in[1];
    const float* b = (const float*)d_in[2];

    cudaFuncSetAttribute(gemm_kernel,
                         cudaFuncAttributeMaxDynamicSharedMemorySize, SMEM_TOTAL);

    reset_kernel<<<1, 32>>>();
    maxabs_kernel<<<1024, 256>>>((const float4*)x, TOT4, 0);
    maxabs_kernel<<<1024, 256>>>((const float4*)W, TOT4, 1);
    maxabs_kernel<<<4, 256>>>((const float4*)b, N_DIM / 4, 2);
    quant_kernel<<<4096, 256>>>((const float4*)x, (const float4*)W, b);
    gemm_kernel<<<dim3(16, 32), 256, SMEM_TOTAL>>>();
    requant_kernel<<<2048, 256>>>((float4*)d_out);
}

// round 6
// speedup vs baseline: 1.3475x; 1.0213x over previous
#include <cuda_runtime.h>
#include <cstdint>

// ============================================================================
// RangeLinearQuantParamLayerWrapper: symmetric 8-bit quantized linear layer
//   1) max|x|, max|W|, max|b|   (single merged kernel)
//   2) quantize x,W -> int8 ; b -> int32 (accumulator scale)
//   3) int8 GEMM (mma.sync m16n8k32 s8) + bias, track max|accum|
//      persistent 148-CTA kernel over 1024 tiles of 128x128 (98.8% balance)
//   4) requantize to 8 bits, dequantize to fp32
// All integer math exact => matches fp32 reference (|accum| << 2^24).
// ============================================================================

#define N_DIM 4096
#define K_DIM 4096
#define TOT   16777216   // 4096*4096
#define TOT4  4194304    // TOT/4
#define NSM   148

// ---------------- scratch (device globals: no runtime allocation) ----------
__device__ signed char g_xq[TOT];      // quantized activations [M,K]
__device__ signed char g_wq[TOT];      // quantized weights     [N,K]
__device__ int         g_bq[N_DIM];    // bias at accumulator scale
__device__ int         g_accum[TOT];   // int32 accumulators
__device__ unsigned    g_max[4];       // 0:max|x| 1:max|W| 2:max|b| 3:max|accum|

// ---------------- kernel 0: reset atomic targets ---------------------------
__global__ void reset_kernel() {
    if (threadIdx.x < 4) g_max[threadIdx.x] = 0u;
}

// ---------------- kernel 1: merged max|.| reduction -------------------------
// blocks [0,1024): x   [1024,2048): W   [2048]: b
__global__ void maxabs_all_kernel(const float4* __restrict__ x,
                                  const float4* __restrict__ W,
                                  const float4* __restrict__ b) {
    const int bid = blockIdx.x;
    const float4* p;
    int n4, slot, gbase, gcount;
    if (bid < 1024)      { p = x; n4 = TOT4;       slot = 0; gbase = bid;        gcount = 1024; }
    else if (bid < 2048) { p = W; n4 = TOT4;       slot = 1; gbase = bid - 1024; gcount = 1024; }
    else                 { p = b; n4 = N_DIM / 4;  slot = 2; gbase = 0;          gcount = 1;    }
    unsigned m = 0u;
    const int stride = gcount * blockDim.x;
    for (int i = gbase * blockDim.x + threadIdx.x; i < n4; i += stride) {
        float4 v = p[i];
        float a = fmaxf(fmaxf(fabsf(v.x), fabsf(v.y)), fmaxf(fabsf(v.z), fabsf(v.w)));
        m = max(m, __float_as_uint(a));   // nonneg floats order as uints
    }
    m = __reduce_max_sync(0xFFFFFFFFu, m);
    if ((threadIdx.x & 31) == 0) atomicMax(&g_max[slot], m);
}

// ---------------- kernel 2: quantize ---------------------------------------
__device__ __forceinline__ signed char q8(float v, float s) {
    float r = rintf(v * s);               // jnp.round = half-to-even = rintf
    r = fminf(fmaxf(r, -128.0f), 127.0f);
    return (signed char)(int)r;
}

__global__ void quant_kernel(const float4* __restrict__ x4,
                             const float4* __restrict__ w4,
                             const float*  __restrict__ b) {
    const float in_scale = 255.0f / (2.0f * __uint_as_float(g_max[0]));
    const float w_scale  = 255.0f / (2.0f * __uint_as_float(g_max[1]));
    char4* xq4 = (char4*)g_xq;
    char4* wq4 = (char4*)g_wq;
    const int stride = gridDim.x * blockDim.x;
    for (int i = blockIdx.x * blockDim.x + threadIdx.x; i < TOT4; i += stride) {
        float4 v = x4[i];
        xq4[i] = make_char4(q8(v.x, in_scale), q8(v.y, in_scale),
                            q8(v.z, in_scale), q8(v.w, in_scale));
        float4 w = w4[i];
        wq4[i] = make_char4(q8(w.x, w_scale), q8(w.y, w_scale),
                            q8(w.z, w_scale), q8(w.w, w_scale));
    }
    const int gid = blockIdx.x * blockDim.x + threadIdx.x;
    if (gid < N_DIM) {
        const float b_scale = 255.0f / (2.0f * __uint_as_float(g_max[2]));
        const float accum_scale = in_scale * w_scale;
        float base = fminf(fmaxf(rintf(b[gid] * b_scale), -128.0f), 127.0f);
        float r = rintf(base * (accum_scale / b_scale));
        g_bq[gid] = (int)r;  // small exact integer
    }
}

// ---------------- kernel 3: persistent int8 GEMM ----------------------------
// 1024 tiles of 128x128; 148 persistent CTAs, 8 warps (2m x 4n), warp 64x32.
#define STAGES      4
#define A_STAGE     16384                    // 128 rows * 128 B
#define STAGE_BYTES 32768                    // A + B
#define SMEM_TOTAL  (STAGES * STAGE_BYTES)   // 131072
#define K_ITERS     32                       // 4096 / 128
#define N_TILES     1024

__device__ __forceinline__ void cp16(uint32_t dst, const void* src) {
    asm volatile("cp.async.cg.shared.global [%0], [%1], 16;" :: "r"(dst), "l"(src));
}

__device__ __forceinline__ void ldm_x4(uint32_t* r, uint32_t addr) {
    asm volatile("ldmatrix.sync.aligned.m8n8.x4.shared.b16 {%0,%1,%2,%3}, [%4];"
                 : "=r"(r[0]), "=r"(r[1]), "=r"(r[2]), "=r"(r[3]) : "r"(addr));
}

__device__ __forceinline__ void mma_s8(int* c, const uint32_t* a,
                                       uint32_t b0, uint32_t b1) {
    asm volatile(
        "mma.sync.aligned.m16n8k32.row.col.s32.s8.s8.s32 "
        "{%0,%1,%2,%3}, {%4,%5,%6,%7}, {%8,%9}, {%0,%1,%2,%3};"
        : "+r"(c[0]), "+r"(c[1]), "+r"(c[2]), "+r"(c[3])
        : "r"(a[0]), "r"(a[1]), "r"(a[2]), "r"(a[3]), "r"(b0), "r"(b1));
}

// swizzled byte offset within a tile of 128B rows
__device__ __forceinline__ uint32_t swz(int row, int kchunk) {
    return (uint32_t)(row * 128 + ((kchunk ^ (row & 7)) << 4));
}

__global__ void __launch_bounds__(256, 1) gemm_kernel() {
    extern __shared__ char smem[];
    const uint32_t sb = (uint32_t)__cvta_generic_to_shared(smem);
    const int tid = threadIdx.x;
    const int lane = tid & 31, wid = tid >> 5;
    const int warp_m = wid >> 2;          // 0..1 (64-row slab)
    const int warp_n = wid & 3;           // 0..3 (32-col slab)

    // cp.async mapping: A 1024 + B 1024 16B-chunks per stage / 256 threads
    const int r0 = tid >> 3;              // 0..31
    const int kc = tid & 7;               // 16B chunk within 128B row
    const size_t gofs = (size_t)r0 * K_DIM + (kc << 4);

    // ldmatrix lane components
    const int a_row = warp_m * 64 + (lane & 7) + ((lane >> 3) & 1) * 8;
    const int a_kch = (lane >> 4) & 1;
    const int b_row = warp_n * 32 + (lane & 7) + ((lane >> 4) & 1) * 8;
    const int b_kch = (lane >> 3) & 1;

    const int g = lane >> 2, t4 = lane & 3;
    unsigned lm = 0u;

    for (int t = blockIdx.x; t < N_TILES; t += gridDim.x) {
        const int m_base = (t >> 5) << 7;     // 32 m-tiles
        const int n_base = (t & 31) << 7;     // 32 n-tiles

        const signed char* Ag = g_xq + (size_t)m_base * K_DIM;
        const signed char* Bg = g_wq + (size_t)n_base * K_DIM;

        auto load_stage = [&](int k) {
            const uint32_t st = sb + (k & (STAGES - 1)) * STAGE_BYTES;
            const int kof = k << 7;
            #pragma unroll
            for (int i = 0; i < 4; i++) {
                cp16(st + swz(r0 + 32 * i, kc),
                     Ag + gofs + (size_t)(32 * i) * K_DIM + kof);
                cp16(st + A_STAGE + swz(r0 + 32 * i, kc),
                     Bg + gofs + (size_t)(32 * i) * K_DIM + kof);
            }
        };

        int acc[4][4][4];
        #pragma unroll
        for (int i = 0; i < 4; i++)
            #pragma unroll
            for (int j = 0; j < 4; j++)
                #pragma unroll
                for (int l = 0; l < 4; l++) acc[i][j][l] = 0;

        load_stage(0); asm volatile("cp.async.commit_group;" ::: "memory");
        load_stage(1); asm volatile("cp.async.commit_group;" ::: "memory");
        load_stage(2); asm volatile("cp.async.commit_group;" ::: "memory");

        uint32_t ar[2][4][4];   // [buf][fm][reg]
        uint32_t br[2][2][4];   // [buf][fp][reg]

        for (int k = 0; k < K_ITERS; k++) {
            asm volatile("cp.async.wait_group 2;" ::: "memory");
            __syncthreads();
            if (k + 3 < K_ITERS) load_stage(k + 3);
            asm volatile("cp.async.commit_group;" ::: "memory");

            const uint32_t sa  = sb + (k & (STAGES - 1)) * STAGE_BYTES;
            const uint32_t sbb = sa + A_STAGE;

            // prefetch ks=0 fragments
            #pragma unroll
            for (int fm = 0; fm < 4; fm++)
                ldm_x4(ar[0][fm], sa  + swz(a_row + fm * 16, a_kch));
            #pragma unroll
            for (int fp = 0; fp < 2; fp++)
                ldm_x4(br[0][fp], sbb + swz(b_row + fp * 16, b_kch));

            #pragma unroll
            for (int ks = 0; ks < 4; ks++) {  // 4 x 32B K-steps per 128B chunk
                const int cur = ks & 1, nxt = cur ^ 1;
                if (ks < 3) {
                    const int kn = (ks + 1) * 2;
                    #pragma unroll
                    for (int fm = 0; fm < 4; fm++)
                        ldm_x4(ar[nxt][fm], sa  + swz(a_row + fm * 16, kn + a_kch));
                    #pragma unroll
                    for (int fp = 0; fp < 2; fp++)
                        ldm_x4(br[nxt][fp], sbb + swz(b_row + fp * 16, kn + b_kch));
                }
                #pragma unroll
                for (int fm = 0; fm < 4; fm++)
                    #pragma unroll
                    for (int fn = 0; fn < 4; fn++)
                        mma_s8(acc[fm][fn], ar[cur][fm],
                               br[cur][fn >> 1][(fn & 1) * 2],
                               br[cur][fn >> 1][(fn & 1) * 2 + 1]);
            }
        }

        // drain outstanding cp.async groups (overlaps with epilogue address
        // math; must complete before smem reuse next tile)
        asm volatile("cp.async.wait_group 0;" ::: "memory");

        // ---- epilogue: bias add, store int32 accum, track max|accum| ------
        const int m0r = m_base + warp_m * 64;
        const int n0c = n_base + warp_n * 32;
        #pragma unroll
        for (int fn = 0; fn < 4; fn++) {
            const int col = n0c + fn * 8 + t4 * 2;
            const int b0v = g_bq[col], b1v = g_bq[col + 1];
            #pragma unroll
            for (int fm = 0; fm < 4; fm++) {
                const int row = m0r + fm * 16 + g;
                int v0 = acc[fm][fn][0] + b0v;
                int v1 = acc[fm][fn][1] + b1v;
                int v2 = acc[fm][fn][2] + b0v;
                int v3 = acc[fm][fn][3] + b1v;
                *(int2*)&g_accum[(size_t)row * N_DIM + col]       = make_int2(v0, v1);
                *(int2*)&g_accum[(size_t)(row + 8) * N_DIM + col] = make_int2(v2, v3);
                lm = max(lm, (unsigned)(v0 < 0 ? -v0 : v0));
                lm = max(lm, (unsigned)(v1 < 0 ? -v1 : v1));
                lm = max(lm, (unsigned)(v2 < 0 ? -v2 : v2));
                lm = max(lm, (unsigned)(v3 < 0 ? -v3 : v3));
            }
        }

        __syncthreads();   // all warps done with this tile's smem
    }

    lm = __reduce_max_sync(0xFFFFFFFFu, lm);
    if (lane == 0) atomicMax(&g_max[3], lm);
}

// ---------------- kernel 4: requantize + dequantize ------------------------
__global__ void requant_kernel(float4* __restrict__ out4) {
    const float in_scale = 255.0f / (2.0f * __uint_as_float(g_max[0]));
    const float w_scale  = 255.0f / (2.0f * __uint_as_float(g_max[1]));
    const float accum_scale = in_scale * w_scale;
    const float max_acc = (float)g_max[3];          // exact (< 2^24)
    const float out_sat = max_acc / accum_scale;
    const float out_scale = 255.0f / (2.0f * out_sat);
    const float ratio = out_scale / accum_scale;
    const int4* a4 = (const int4*)g_accum;
    const int stride = gridDim.x * blockDim.x;
    for (int i = blockIdx.x * blockDim.x + threadIdx.x; i < TOT4; i += stride) {
        int4 a = a4[i];
        float4 o;
        o.x = fminf(fmaxf(rintf((float)a.x * ratio), -128.0f), 127.0f) / out_scale;
        o.y = fminf(fmaxf(rintf((float)a.y * ratio), -128.0f), 127.0f) / out_scale;
        o.z = fminf(fmaxf(rintf((float)a.z * ratio), -128.0f), 127.0f) / out_scale;
        o.w = fminf(fmaxf(rintf((float)a.w * ratio), -128.0f), 127.0f) / out_scale;
        out4[i] = o;
    }
}

// ---------------- launch ----------------------------------------------------
extern "C" void kernel_launch(void* const* d_in, const int* in_sizes, int n_in,
                              void* d_out, int out_size) {
    const float* x = (const float*)d_in[0];
    const float* W = (const float*)d_in[1];
    const float* b = (const float*)d_in[2];

    cudaFuncSetAttribute(gemm_kernel,
                         cudaFuncAttributeMaxDynamicSharedMemorySize, SMEM_TOTAL);

    reset_kernel<<<1, 32>>>();
    maxabs_all_kernel<<<2049, 256>>>((const float4*)x, (const float4*)W,
                                     (const float4*)b);
    quant_kernel<<<4096, 256>>>((const float4*)x, (const float4*)W, b);
    gemm_kernel<<<NSM, 256, SMEM_TOTAL>>>();
    requant_kernel<<<2048, 256>>>((float4*)d_out);
}

// round 7
// speedup vs baseline: 1.3648x; 1.0128x over previous
#include <cuda_runtime.h>
#include <cstdint>

// ============================================================================
// RangeLinearQuantParamLayerWrapper: symmetric 8-bit quantized linear layer
//   1) max|x|, max|W|, max|b|   (single merged kernel)
//   2) quantize x,W -> int8 ; b -> int32 (accumulator scale)
//   3) int8 GEMM (mma.sync m16n8k32 s8) + bias, track max|accum|
//      persistent 296-CTA kernel (2 CTAs/SM, 4 warps/SMSP) over 1024 tiles
//   4) requantize to 8 bits, dequantize to fp32
// All integer math exact => matches fp32 reference (|accum| << 2^24).
// ============================================================================

#define N_DIM 4096
#define K_DIM 4096
#define TOT   16777216   // 4096*4096
#define TOT4  4194304    // TOT/4
#define NSM   148

// ---------------- scratch (device globals: no runtime allocation) ----------
__device__ signed char g_xq[TOT];      // quantized activations [M,K]
__device__ signed char g_wq[TOT];      // quantized weights     [N,K]
__device__ int         g_bq[N_DIM];    // bias at accumulator scale
__device__ int         g_accum[TOT];   // int32 accumulators
__device__ unsigned    g_max[4];       // 0:max|x| 1:max|W| 2:max|b| 3:max|accum|

// ---------------- kernel 0: reset atomic targets ---------------------------
__global__ void reset_kernel() {
    if (threadIdx.x < 4) g_max[threadIdx.x] = 0u;
}

// ---------------- kernel 1: merged max|.| reduction -------------------------
// blocks [0,1024): x   [1024,2048): W   [2048]: b
__global__ void maxabs_all_kernel(const float4* __restrict__ x,
                                  const float4* __restrict__ W,
                                  const float4* __restrict__ b) {
    const int bid = blockIdx.x;
    const float4* p;
    int n4, slot, gbase, gcount;
    if (bid < 1024)      { p = x; n4 = TOT4;       slot = 0; gbase = bid;        gcount = 1024; }
    else if (bid < 2048) { p = W; n4 = TOT4;       slot = 1; gbase = bid - 1024; gcount = 1024; }
    else                 { p = b; n4 = N_DIM / 4;  slot = 2; gbase = 0;          gcount = 1;    }
    unsigned m = 0u;
    const int stride = gcount * blockDim.x;
    for (int i = gbase * blockDim.x + threadIdx.x; i < n4; i += stride) {
        float4 v = p[i];
        float a = fmaxf(fmaxf(fabsf(v.x), fabsf(v.y)), fmaxf(fabsf(v.z), fabsf(v.w)));
        m = max(m, __float_as_uint(a));   // nonneg floats order as uints
    }
    m = __reduce_max_sync(0xFFFFFFFFu, m);
    if ((threadIdx.x & 31) == 0) atomicMax(&g_max[slot], m);
}

// ---------------- kernel 2: quantize ---------------------------------------
__device__ __forceinline__ signed char q8(float v, float s) {
    float r = rintf(v * s);               // jnp.round = half-to-even = rintf
    r = fminf(fmaxf(r, -128.0f), 127.0f);
    return (signed char)(int)r;
}

__global__ void quant_kernel(const float4* __restrict__ x4,
                             const float4* __restrict__ w4,
                             const float*  __restrict__ b) {
    const float in_scale = 255.0f / (2.0f * __uint_as_float(g_max[0]));
    const float w_scale  = 255.0f / (2.0f * __uint_as_float(g_max[1]));
    char4* xq4 = (char4*)g_xq;
    char4* wq4 = (char4*)g_wq;
    const int stride = gridDim.x * blockDim.x;
    for (int i = blockIdx.x * blockDim.x + threadIdx.x; i < TOT4; i += stride) {
        float4 v = x4[i];
        xq4[i] = make_char4(q8(v.x, in_scale), q8(v.y, in_scale),
                            q8(v.z, in_scale), q8(v.w, in_scale));
        float4 w = w4[i];
        wq4[i] = make_char4(q8(w.x, w_scale), q8(w.y, w_scale),
                            q8(w.z, w_scale), q8(w.w, w_scale));
    }
    const int gid = blockIdx.x * blockDim.x + threadIdx.x;
    if (gid < N_DIM) {
        const float b_scale = 255.0f / (2.0f * __uint_as_float(g_max[2]));
        const float accum_scale = in_scale * w_scale;
        float base = fminf(fmaxf(rintf(b[gid] * b_scale), -128.0f), 127.0f);
        float r = rintf(base * (accum_scale / b_scale));
        g_bq[gid] = (int)r;  // small exact integer
    }
}

// ---------------- kernel 3: persistent int8 GEMM ----------------------------
// 1024 tiles of 128x128; 296 persistent CTAs (2/SM), 8 warps (2m x 4n),
// warp tile 64x32, 3-stage cp.async pipeline, no frag double-buffer
// (latency hidden by 4 warps/SMSP).
#define STAGES      3
#define A_STAGE     16384                    // 128 rows * 128 B
#define STAGE_BYTES 32768                    // A + B
#define SMEM_TOTAL  (STAGES * STAGE_BYTES)   // 98304
#define K_ITERS     32                       // 4096 / 128
#define N_TILES     1024

__device__ __forceinline__ void cp16(uint32_t dst, const void* src) {
    asm volatile("cp.async.cg.shared.global [%0], [%1], 16;" :: "r"(dst), "l"(src));
}

__device__ __forceinline__ void ldm_x4(uint32_t* r, uint32_t addr) {
    asm volatile("ldmatrix.sync.aligned.m8n8.x4.shared.b16 {%0,%1,%2,%3}, [%4];"
                 : "=r"(r[0]), "=r"(r[1]), "=r"(r[2]), "=r"(r[3]) : "r"(addr));
}

__device__ __forceinline__ void mma_s8(int* c, const uint32_t* a,
                                       uint32_t b0, uint32_t b1) {
    asm volatile(
        "mma.sync.aligned.m16n8k32.row.col.s32.s8.s8.s32 "
        "{%0,%1,%2,%3}, {%4,%5,%6,%7}, {%8,%9}, {%0,%1,%2,%3};"
        : "+r"(c[0]), "+r"(c[1]), "+r"(c[2]), "+r"(c[3])
        : "r"(a[0]), "r"(a[1]), "r"(a[2]), "r"(a[3]), "r"(b0), "r"(b1));
}

// swizzled byte offset within a tile of 128B rows
__device__ __forceinline__ uint32_t swz(int row, int kchunk) {
    return (uint32_t)(row * 128 + ((kchunk ^ (row & 7)) << 4));
}

__global__ void __launch_bounds__(256, 2) gemm_kernel() {
    extern __shared__ char smem[];
    const uint32_t sb = (uint32_t)__cvta_generic_to_shared(smem);
    const int tid = threadIdx.x;
    const int lane = tid & 31, wid = tid >> 5;
    const int warp_m = wid >> 2;          // 0..1 (64-row slab)
    const int warp_n = wid & 3;           // 0..3 (32-col slab)

    // cp.async mapping: A 1024 + B 1024 16B-chunks per stage / 256 threads
    const int r0 = tid >> 3;              // 0..31
    const int kc = tid & 7;               // 16B chunk within 128B row
    const size_t gofs = (size_t)r0 * K_DIM + (kc << 4);

    // ldmatrix lane components
    const int a_row = warp_m * 64 + (lane & 7) + ((lane >> 3) & 1) * 8;
    const int a_kch = (lane >> 4) & 1;
    const int b_row = warp_n * 32 + (lane & 7) + ((lane >> 4) & 1) * 8;
    const int b_kch = (lane >> 3) & 1;

    const int g = lane >> 2, t4 = lane & 3;
    unsigned lm = 0u;

    for (int t = blockIdx.x; t < N_TILES; t += gridDim.x) {
        const int m_base = (t >> 5) << 7;     // 32 m-tiles
        const int n_base = (t & 31) << 7;     // 32 n-tiles

        const signed char* Ag = g_xq + (size_t)m_base * K_DIM;
        const signed char* Bg = g_wq + (size_t)n_base * K_DIM;

        auto load_stage = [&](int k) {
            const uint32_t st = sb + (k % STAGES) * STAGE_BYTES;
            const int kof = k << 7;
            #pragma unroll
            for (int i = 0; i < 4; i++) {
                cp16(st + swz(r0 + 32 * i, kc),
                     Ag + gofs + (size_t)(32 * i) * K_DIM + kof);
                cp16(st + A_STAGE + swz(r0 + 32 * i, kc),
                     Bg + gofs + (size_t)(32 * i) * K_DIM + kof);
            }
        };

        int acc[4][4][4];
        #pragma unroll
        for (int i = 0; i < 4; i++)
            #pragma unroll
            for (int j = 0; j < 4; j++)
                #pragma unroll
                for (int l = 0; l < 4; l++) acc[i][j][l] = 0;

        load_stage(0); asm volatile("cp.async.commit_group;" ::: "memory");
        load_stage(1); asm volatile("cp.async.commit_group;" ::: "memory");

        for (int k = 0; k < K_ITERS; k++) {
            asm volatile("cp.async.wait_group 1;" ::: "memory");  // stage k ready
            __syncthreads();
            if (k + 2 < K_ITERS) load_stage(k + 2);
            asm volatile("cp.async.commit_group;" ::: "memory");

            const uint32_t sa  = sb + (k % STAGES) * STAGE_BYTES;
            const uint32_t sbb = sa + A_STAGE;

            #pragma unroll
            for (int ks = 0; ks < 4; ks++) {  // 4 x 32B K-steps per 128B chunk
                uint32_t ar[4][4];
                #pragma unroll
                for (int fm = 0; fm < 4; fm++)
                    ldm_x4(ar[fm], sa  + swz(a_row + fm * 16, ks * 2 + a_kch));
                uint32_t br[2][4];
                #pragma unroll
                for (int fp = 0; fp < 2; fp++)
                    ldm_x4(br[fp], sbb + swz(b_row + fp * 16, ks * 2 + b_kch));
                #pragma unroll
                for (int fm = 0; fm < 4; fm++)
                    #pragma unroll
                    for (int fn = 0; fn < 4; fn++)
                        mma_s8(acc[fm][fn], ar[fm],
                               br[fn >> 1][(fn & 1) * 2],
                               br[fn >> 1][(fn & 1) * 2 + 1]);
            }
            __syncthreads();   // all warps done reading stage k before reuse
        }

        // ---- epilogue: bias add, store int32 accum, track max|accum| ------
        const int m0r = m_base + warp_m * 64;
        const int n0c = n_base + warp_n * 32;
        #pragma unroll
        for (int fn = 0; fn < 4; fn++) {
            const int col = n0c + fn * 8 + t4 * 2;
            const int b0v = g_bq[col], b1v = g_bq[col + 1];
            #pragma unroll
            for (int fm = 0; fm < 4; fm++) {
                const int row = m0r + fm * 16 + g;
                int v0 = acc[fm][fn][0] + b0v;
                int v1 = acc[fm][fn][1] + b1v;
                int v2 = acc[fm][fn][2] + b0v;
                int v3 = acc[fm][fn][3] + b1v;
                *(int2*)&g_accum[(size_t)row * N_DIM + col]       = make_int2(v0, v1);
                *(int2*)&g_accum[(size_t)(row + 8) * N_DIM + col] = make_int2(v2, v3);
                lm = max(lm, (unsigned)(v0 < 0 ? -v0 : v0));
                lm = max(lm, (unsigned)(v1 < 0 ? -v1 : v1));
                lm = max(lm, (unsigned)(v2 < 0 ? -v2 : v2));
                lm = max(lm, (unsigned)(v3 < 0 ? -v3 : v3));
            }
        }

        // drain leftover (possibly empty) cp.async groups before next tile
        asm volatile("cp.async.wait_group 0;" ::: "memory");
        __syncthreads();
    }

    lm = __reduce_max_sync(0xFFFFFFFFu, lm);
    if (lane == 0) atomicMax(&g_max[3], lm);
}

// ---------------- kernel 4: requantize + dequantize ------------------------
__global__ void requant_kernel(float4* __restrict__ out4) {
    const float in_scale = 255.0f / (2.0f * __uint_as_float(g_max[0]));
    const float w_scale  = 255.0f / (2.0f * __uint_as_float(g_max[1]));
    const float accum_scale = in_scale * w_scale;
    const float max_acc = (float)g_max[3];          // exact (< 2^24)
    const float out_sat = max_acc / accum_scale;
    const float out_scale = 255.0f / (2.0f * out_sat);
    const float ratio = out_scale / accum_scale;
    const int4* a4 = (const int4*)g_accum;
    const int stride = gridDim.x * blockDim.x;
    for (int i = blockIdx.x * blockDim.x + threadIdx.x; i < TOT4; i += stride) {
        int4 a = a4[i];
        float4 o;
        o.x = fminf(fmaxf(rintf((float)a.x * ratio), -128.0f), 127.0f) / out_scale;
        o.y = fminf(fmaxf(rintf((float)a.y * ratio), -128.0f), 127.0f) / out_scale;
        o.z = fminf(fmaxf(rintf((float)a.z * ratio), -128.0f), 127.0f) / out_scale;
        o.w = fminf(fmaxf(rintf((float)a.w * ratio), -128.0f), 127.0f) / out_scale;
        out4[i] = o;
    }
}

// ---------------- launch ----------------------------------------------------
extern "C" void kernel_launch(void* const* d_in, const int* in_sizes, int n_in,
                              void* d_out, int out_size) {
    const float* x = (const float*)d_in[0];
    const float* W = (const float*)d_in[1];
    const float* b = (const float*)d_in[2];

    cudaFuncSetAttribute(gemm_kernel,
                         cudaFuncAttributeMaxDynamicSharedMemorySize, SMEM_TOTAL);

    reset_kernel<<<1, 32>>>();
    maxabs_all_kernel<<<2049, 256>>>((const float4*)x, (const float4*)W,
                                     (const float4*)b);
    quant_kernel<<<4096, 256>>>((const float4*)x, (const float4*)W, b);
    gemm_kernel<<<2 * NSM, 256, SMEM_TOTAL>>>();
    requant_kernel<<<2048, 256>>>((float4*)d_out);
}